// round 2
// baseline (speedup 1.0000x reference)
#include <cuda_runtime.h>
#include <math.h>

// Problem constants
#define Bb   2
#define Tt   2048
#define Vv   32000
#define Dd   1024
#define Ff   256
#define NLl  6
#define LATl 64
#define Mrows (Bb*Tt)          // 4096 token rows

// ---------------- scratch (static __device__, no allocs) ----------------
__device__ float g_h[Mrows*Dd];        // residual stream
__device__ float g_xn[Mrows*Dd];       // layernorm output
__device__ float g_u[Mrows*Dd];        // gated input
__device__ float g_y[Mrows*Dd];        // spec_out result
__device__ float g_concept[Mrows*Dd];  // VIB decoder output
__device__ float g_buf1[Mrows*4*Dd];   // big scratch: gate/ogate pre, ffn hidden
__device__ float g_sp[Mrows*2*Ff];     // spectral input (u_r|u_i)
__device__ float g_ycat[Mrows*2*Ff];   // scan output (y_r|y_i)
__device__ float g_decay[Mrows*Ff];    // sigmoid(decay pre)
__device__ float g_params[Mrows*2*LATl]; // mu|logvar
__device__ float g_accum;              // KL sum

// ---------------- helpers ----------------
__inline__ __device__ float warpsum(float v) {
#pragma unroll
    for (int o = 16; o > 0; o >>= 1) v += __shfl_xor_sync(0xffffffffu, v, o);
    return v;
}

__inline__ __device__ float sigmoidf_(float x) { return 1.0f / (1.0f + expf(-x)); }
__inline__ __device__ float geluf_(float x) { return 0.5f * x * (1.0f + erff(x * 0.70710678118654752f)); }

// ---------------- embed ----------------
__global__ void embed_kernel(const int* __restrict__ x, const float* __restrict__ emb) {
    int row = blockIdx.x;
    int tok = x[row];
    size_t src = (size_t)tok * Dd, dst = (size_t)row * Dd;
#pragma unroll
    for (int i = 0; i < 4; i++) {
        int c = threadIdx.x + i * 256;
        g_h[dst + c] = emb[src + c];
    }
}

// ---------------- layernorm (optionally in + in2) ----------------
__global__ void __launch_bounds__(256) layernorm_kernel(
    const float* __restrict__ in, const float* __restrict__ in2,
    const float* __restrict__ g, const float* __restrict__ bb,
    float* __restrict__ out)
{
    int row = blockIdx.x;
    size_t base = (size_t)row * Dd;
    float vals[4];
    float s = 0.f, s2 = 0.f;
#pragma unroll
    for (int i = 0; i < 4; i++) {
        int c = threadIdx.x + i * 256;
        float v = in[base + c];
        if (in2) v += in2[base + c];
        vals[i] = v; s += v; s2 += v * v;
    }
    __shared__ float sh1[8], sh2[8];
    s = warpsum(s); s2 = warpsum(s2);
    int w = threadIdx.x >> 5, l = threadIdx.x & 31;
    if (l == 0) { sh1[w] = s; sh2[w] = s2; }
    __syncthreads();
    if (w == 0) {
        float a = (l < 8) ? sh1[l] : 0.f;
        float b2 = (l < 8) ? sh2[l] : 0.f;
        a = warpsum(a); b2 = warpsum(b2);
        if (l == 0) { sh1[0] = a; sh2[0] = b2; }
    }
    __syncthreads();
    float mean = sh1[0] * (1.f / Dd);
    float var  = sh2[0] * (1.f / Dd) - mean * mean;
    float inv  = rsqrtf(var + 1e-5f);
#pragma unroll
    for (int i = 0; i < 4; i++) {
        int c = threadIdx.x + i * 256;
        out[base + c] = (vals[i] - mean) * inv * g[c] + bb[c];
    }
}

// ---------------- SGEMM: C[m,n] = act( sum_k A[m,k]*B[n,k] + bias[n] ) (+= if addC)
// A: M x K (row stride ldA), B: N x K (packed), C: M x N (packed).
// Requires M%128==0, N%128==0, K%8==0.
__global__ void __launch_bounds__(256) gemm_nt(
    const float* __restrict__ A, const float* __restrict__ B,
    const float* __restrict__ bias, float* __restrict__ C,
    int M, int N, int K, int ldA, int act, int addC)
{
    __shared__ float As[8][128];
    __shared__ float Bs[8][128];
    int tid = threadIdx.x;
    int tx = tid & 15, ty = tid >> 4;
    int rowBase = blockIdx.y * 128;
    int colBase = blockIdx.x * 128;

    float acc[8][8];
#pragma unroll
    for (int i = 0; i < 8; i++)
#pragma unroll
        for (int j = 0; j < 8; j++) acc[i][j] = 0.f;

    int ra = tid >> 1;           // 0..127 tile row
    int ka = (tid & 1) * 4;      // 0 or 4
    const float* Ap = A + (size_t)(rowBase + ra) * ldA + ka;
    const float* Bp = B + (size_t)(colBase + ra) * K + ka;

    for (int k0 = 0; k0 < K; k0 += 8) {
        float4 av = *(const float4*)(Ap + k0);
        float4 bv = *(const float4*)(Bp + k0);
        As[ka + 0][ra] = av.x; As[ka + 1][ra] = av.y;
        As[ka + 2][ra] = av.z; As[ka + 3][ra] = av.w;
        Bs[ka + 0][ra] = bv.x; Bs[ka + 1][ra] = bv.y;
        Bs[ka + 2][ra] = bv.z; Bs[ka + 3][ra] = bv.w;
        __syncthreads();
#pragma unroll
        for (int kk = 0; kk < 8; kk++) {
            float a[8], b[8];
#pragma unroll
            for (int i = 0; i < 8; i++) a[i] = As[kk][ty * 8 + i];
#pragma unroll
            for (int j = 0; j < 8; j++) b[j] = Bs[kk][tx * 8 + j];
#pragma unroll
            for (int i = 0; i < 8; i++)
#pragma unroll
                for (int j = 0; j < 8; j++) acc[i][j] += a[i] * b[j];
        }
        __syncthreads();
    }

#pragma unroll
    for (int i = 0; i < 8; i++) {
        int r = rowBase + ty * 8 + i;
#pragma unroll
        for (int j = 0; j < 8; j++) {
            int c = colBase + tx * 8 + j;
            float v = acc[i][j];
            if (bias) v += bias[c];
            if (act == 1) v = sigmoidf_(v);
            else if (act == 2) v = geluf_(v);
            size_t idx = (size_t)r * N + c;
            if (addC) C[idx] += v; else C[idx] = v;
        }
    }
}

// ---------------- elementwise ----------------
__global__ void mul_kernel(const float* __restrict__ a, const float* __restrict__ b,
                           float* __restrict__ o, int n) {
    int i = blockIdx.x * blockDim.x + threadIdx.x;
    if (i < n) o[i] = a[i] * b[i];
}

__global__ void fma_add_kernel(float* __restrict__ h, const float* __restrict__ y,
                               const float* __restrict__ s, int n) {
    int i = blockIdx.x * blockDim.x + threadIdx.x;
    if (i < n) h[i] += y[i] * s[i];
}

// ---------------- sequential complex scan over time ----------------
// y_t = a_t * y_{t-1} + u_t  (complex), per (batch, feature) channel.
__global__ void scan_kernel(const float* __restrict__ freq) {
    int tidg = blockIdx.x * blockDim.x + threadIdx.x;
    if (tidg >= Bb * Ff) return;
    int b = tidg / Ff, f = tidg % Ff;
    float w = 0.1f * freq[f];
    float cw = cosf(w), sw = sinf(w);
    float yr = 0.f, yi = 0.f;
    size_t baseF  = (size_t)b * Tt * Ff + f;
    size_t base2F = (size_t)b * Tt * 2 * Ff + f;
    for (int t = 0; t < Tt; t++) {
        float d  = g_decay[baseF + (size_t)t * Ff];
        float ur = g_sp[base2F + (size_t)t * 2 * Ff];
        float ui = g_sp[base2F + (size_t)t * 2 * Ff + Ff];
        float ar = d * cw, ai = d * sw;
        float nyr = ar * yr - ai * yi + ur;
        float nyi = ar * yi + ai * yr + ui;
        yr = nyr; yi = nyi;
        g_ycat[base2F + (size_t)t * 2 * Ff]      = yr;
        g_ycat[base2F + (size_t)t * 2 * Ff + Ff] = yi;
    }
}

// ---------------- KL regularizer ----------------
__global__ void kl_zero_kernel() { g_accum = 0.f; }

__global__ void __launch_bounds__(256) kl_reduce_kernel() {
    int i = blockIdx.x * blockDim.x + threadIdx.x;
    float v = 0.f;
    if (i < Mrows * LATl) {
        int row = i / LATl, l = i % LATl;
        float mu = g_params[(size_t)row * (2 * LATl) + l];
        float lv = g_params[(size_t)row * (2 * LATl) + LATl + l];
        v = -0.5f * (1.f + lv - mu * mu - expf(lv));
    }
    v = warpsum(v);
    __shared__ float sh[8];
    int w = threadIdx.x >> 5, l = threadIdx.x & 31;
    if (l == 0) sh[w] = v;
    __syncthreads();
    if (w == 0) {
        float a = (l < 8) ? sh[l] : 0.f;
        a = warpsum(a);
        if (l == 0) atomicAdd(&g_accum, a);
    }
}

__global__ void kl_final_kernel(float* __restrict__ out, int do_write) {
    if (do_write) {
        float mean = g_accum * (1.f / (float)(Mrows * LATl));
        out[0] = 0.01f * fmaxf(mean, 0.05f);
    }
}

// ---------------- host orchestration ----------------
static void launch_gemm(const float* A, const float* B, const float* bias, float* C,
                        int M, int N, int K, int ldA, int act, int addC) {
    dim3 grid(N / 128, M / 128);
    gemm_nt<<<grid, 256>>>(A, B, bias, C, M, N, K, ldA, act, addC);
}

extern "C" void kernel_launch(void* const* d_in, const int* in_sizes, int n_in,
                              void* d_out, int out_size) {
    (void)in_sizes; (void)n_in;
    const int*   x         = (const int*)  d_in[0];
    const float* emb       = (const float*)d_in[1];
    const float* freq      = (const float*)d_in[2];
    const float* decay_W   = (const float*)d_in[3];
    const float* decay_b   = (const float*)d_in[4];
    const float* spec_in_W = (const float*)d_in[5];
    const float* spec_out_W= (const float*)d_in[6];
    const float* norm1_g   = (const float*)d_in[7];
    const float* norm1_b   = (const float*)d_in[8];
    const float* gate_W    = (const float*)d_in[9];
    const float* gate_b    = (const float*)d_in[10];
    const float* ogate_W   = (const float*)d_in[11];
    const float* ogate_b   = (const float*)d_in[12];
    const float* ffn_g     = (const float*)d_in[13];
    const float* ffn_b     = (const float*)d_in[14];
    const float* ffn_W1    = (const float*)d_in[15];
    const float* ffn_b1    = (const float*)d_in[16];
    const float* ffn_W2    = (const float*)d_in[17];
    const float* ffn_b2    = (const float*)d_in[18];
    const float* vib_g     = (const float*)d_in[19];
    const float* vib_b     = (const float*)d_in[20];
    const float* enc_W     = (const float*)d_in[21];
    const float* enc_b     = (const float*)d_in[22];
    const float* dec_W     = (const float*)d_in[23];
    const float* dec_b     = (const float*)d_in[24];
    const float* normf_g   = (const float*)d_in[25];
    const float* normf_b   = (const float*)d_in[26];
    float* logits = (float*)d_out;

    // resolve scratch symbol addresses (host API, graph-safe, no allocation)
    float *p_h, *p_xn, *p_u, *p_y, *p_concept, *p_buf1, *p_sp, *p_ycat, *p_decay, *p_params;
    cudaGetSymbolAddress((void**)&p_h,       g_h);
    cudaGetSymbolAddress((void**)&p_xn,      g_xn);
    cudaGetSymbolAddress((void**)&p_u,       g_u);
    cudaGetSymbolAddress((void**)&p_y,       g_y);
    cudaGetSymbolAddress((void**)&p_concept, g_concept);
    cudaGetSymbolAddress((void**)&p_buf1,    g_buf1);
    cudaGetSymbolAddress((void**)&p_sp,      g_sp);
    cudaGetSymbolAddress((void**)&p_ycat,    g_ycat);
    cudaGetSymbolAddress((void**)&p_decay,   g_decay);
    cudaGetSymbolAddress((void**)&p_params,  g_params);

    const int NE = Mrows * Dd;                 // 4M elems
    const int EW_BLOCKS = NE / 256;

    // h = emb[x]
    embed_kernel<<<Mrows, 256>>>(x, emb);

    for (int i = 0; i < NLl; i++) {
        const float* gW  = gate_W  + (size_t)i * Dd * Dd;
        const float* ogW = ogate_W + (size_t)i * Dd * Dd;
        const float* dW  = decay_W + (size_t)i * Ff * Dd;
        const float* siW = spec_in_W  + (size_t)i * 2 * Ff * Dd;
        const float* soW = spec_out_W + (size_t)i * Dd * 2 * Ff;
        const float* w1  = ffn_W1 + (size_t)i * 4 * Dd * Dd;
        const float* w2  = ffn_W2 + (size_t)i * Dd * 4 * Dd;

        // xn = LN(h)
        layernorm_kernel<<<Mrows, 256>>>(p_h, nullptr, norm1_g + i * Dd, norm1_b + i * Dd, p_xn);
        // buf1 = sigmoid(xn @ gate_W.T + gate_b)
        launch_gemm(p_xn, gW, gate_b + i * Dd, p_buf1, Mrows, Dd, Dd, Dd, 1, 0);
        // u = xn * buf1
        mul_kernel<<<EW_BLOCKS, 256>>>(p_xn, p_buf1, p_u, NE);
        // decay = sigmoid(u @ decay_W.T + decay_b)
        launch_gemm(p_u, dW, decay_b + i * Ff, p_decay, Mrows, Ff, Dd, Dd, 1, 0);
        // sp = u @ spec_in_W.T
        launch_gemm(p_u, siW, nullptr, p_sp, Mrows, 2 * Ff, Dd, Dd, 0, 0);
        // complex linear recurrence over time
        scan_kernel<<<2, 256>>>(freq + i * Ff);
        // y = ycat @ spec_out_W.T
        launch_gemm(p_ycat, soW, nullptr, p_y, Mrows, Dd, 2 * Ff, 2 * Ff, 0, 0);
        // buf1 = sigmoid(xn @ ogate_W.T + ogate_b)
        launch_gemm(p_xn, ogW, ogate_b + i * Dd, p_buf1, Mrows, Dd, Dd, Dd, 1, 0);
        // h += y * buf1
        fma_add_kernel<<<EW_BLOCKS, 256>>>(p_h, p_y, p_buf1, NE);
        // xn = LN(h) (ffn norm)
        layernorm_kernel<<<Mrows, 256>>>(p_h, nullptr, ffn_g + i * Dd, ffn_b + i * Dd, p_xn);
        // buf1 = gelu(xn @ W1.T + b1)
        launch_gemm(p_xn, w1, ffn_b1 + i * 4 * Dd, p_buf1, Mrows, 4 * Dd, Dd, Dd, 2, 0);
        // h += buf1 @ W2.T + b2
        launch_gemm(p_buf1, w2, ffn_b2 + i * Dd, p_h, Mrows, Dd, 4 * Dd, 4 * Dd, 0, 1);
    }

    // VIB head
    layernorm_kernel<<<Mrows, 256>>>(p_h, nullptr, vib_g, vib_b, p_xn);
    // params = xn @ enc_W.T + enc_b   (N = 2*LAT = 128)
    launch_gemm(p_xn, enc_W, enc_b, p_params, Mrows, 2 * LATl, Dd, Dd, 0, 0);
    // concept = gelu(mu @ dec_W.T + dec_b)  (mu = params[:, :64], ldA = 128, K = 64)
    launch_gemm(p_params, dec_W, dec_b, p_concept, Mrows, Dd, LATl, 2 * LATl, 2, 0);
    // out = LN(h + concept)
    layernorm_kernel<<<Mrows, 256>>>(p_h, p_concept, normf_g, normf_b, p_xn);
    // logits = out @ emb.T
    launch_gemm(p_xn, emb, nullptr, logits, Mrows, Vv, Dd, Dd, 0, 0);

    // reg_loss (written after logits if the output buffer carries it)
    kl_zero_kernel<<<1, 1>>>();
    kl_reduce_kernel<<<(Mrows * LATl + 255) / 256, 256>>>();
    int do_write = (out_size >= Mrows * Vv + 1) ? 1 : 0;
    kl_final_kernel<<<1, 1>>>(logits + (size_t)Mrows * Vv, do_write);
}